// round 14
// baseline (speedup 1.0000x reference)
#include <cuda_runtime.h>
#include <cuda_bf16.h>
#include <math.h>
#include <stdint.h>

#define BB 64
#define TT 32
#define CC 2048
#define DD 1024

// Scratch (__device__ globals; allocation-free rule)
__device__ float g_H [TT * BB * DD];
__device__ float g_H2[TT * BB * DD];
__device__ float g_Z [TT * BB * DD];
__device__ float g_G [TT * BB * DD];

__device__ __forceinline__ float gelu_f(float x) {
    return 0.5f * x * (1.0f + erff(x * 0.70710678118654752440f));
}

// pack two floats -> bf16x2 word: lo16 = bf16(e), hi16 = bf16(o)
__device__ __forceinline__ uint32_t pkbf(float o, float e) {
    uint32_t r;
    asm("cvt.rn.bf16x2.f32 %0, %1, %2;" : "=r"(r) : "f"(o), "f"(e));
    return r;
}
// unpack bf16x2 word -> two floats (e = lo half, o = hi half)
__device__ __forceinline__ float2 upbf(uint32_t w) {
    __nv_bfloat162 h = *reinterpret_cast<__nv_bfloat162*>(&w);
    return __bfloat1622float2(h);
}

// acc += A(16x16 bf16) @ B(16x8 bf16), fp32 accum
#define MMA_BF16(c, a0, a1, a2, a3, b0, b1) \
    asm volatile("mma.sync.aligned.m16n8k16.row.col.f32.bf16.bf16.f32 " \
                 "{%0,%1,%2,%3}, {%4,%5,%6,%7}, {%8,%9}, {%0,%1,%2,%3};" \
                 : "+f"((c)[0]), "+f"((c)[1]), "+f"((c)[2]), "+f"((c)[3]) \
                 : "r"(a0), "r"(a1), "r"(a2), "r"(a3), "r"(b0), "r"(b1))

// Per-stage layout (32-bit words): A hi [16][72], A lo, W hi [16][136], W lo.
#define AHI_OFF 0
#define ALO_OFF 1152           // 16*72
#define WHI_OFF 2304
#define WLO_OFF 4480           // + 16*136
#define STAGE_WORDS 6656
#define SM_WORDS 13312         // 2 stages (epilogue 64*132=8448 fits inside)
#define A2_PAD 72
#define W2_PAD 136
#define C_PAD 132

// ---------------------------------------------------------------------------
// Batched GEMM via 3x-split bf16 mma.sync m16n8k16, double-buffered smem:
//   C[t](64 x N) = Act[t](64 x K) @ W[t](K x N)
// Block: 256 thr, tile 64m x 128n, BK=32 (2 k16-steps).
// MIX: A := Act2*1e-4 + Act*(1-1e-4) on load (fused input-noise for enc1).
// MMA issue is TERM-MAJOR: all 8 independent accumulators per split term,
// so consecutive tensor ops never share an accumulator (no RAW stalls).
// ---------------------------------------------------------------------------
template<bool GELU_EPI, bool MIX>
__global__ __launch_bounds__(256, 2) void gemm_mma(
    const float* __restrict__ Act, const float* __restrict__ Act2,
    long act_t, int act_ld,
    const float* __restrict__ W, int N, int K,
    float* __restrict__ C, long c_t, int c_ld)
{
    extern __shared__ __align__(16) uint32_t sm[];
    const int t     = blockIdx.y;
    const int ntile = blockIdx.x;
    const int tid   = threadIdx.x;
    const int wid   = tid >> 5;
    const int lid   = tid & 31;
    const int wm    = wid & 1;
    const int wn    = wid >> 1;
    const int g     = lid >> 2;
    const int tg    = lid & 3;

    const float* At  = Act + (long)t * act_t;
    const float* At2 = MIX ? (Act2 + (long)t * act_t) : nullptr;
    const float* Wt  = W + (long)t * K * N + ntile * 128;

    float acc[2][4][4];
    #pragma unroll
    for (int i = 0; i < 2; i++)
        #pragma unroll
        for (int j = 0; j < 4; j++)
            #pragma unroll
            for (int r = 0; r < 4; r++) acc[i][j][r] = 0.f;

    // global load maps
    const int s_ar = tid >> 2;             // A row 0..63
    const int s_ak = (tid & 3) * 8;        // A k base (8 floats = 4 pairs)
    const int s_wp = tid >> 4;             // W k-pair 0..15 (rows 2p, 2p+1)
    const int s_wn = (tid & 15) * 8;       // W n base (8 floats)
    const int a_jb = s_ak >> 1;            // A k-pair base 0,4,8,12

    // ---- prefetch chunk 0
    float4 va0, va1, we0, we1, wo0, wo1;
    {
        const float* ap = At + (long)s_ar * act_ld + s_ak;
        va0 = *(const float4*)(ap);
        va1 = *(const float4*)(ap + 4);
        if (MIX) {
            const float* np = At2 + (long)s_ar * act_ld + s_ak;
            float4 n0 = *(const float4*)(np);
            float4 n1 = *(const float4*)(np + 4);
            const float f = 1e-4f, gf = 1.0f - 1e-4f;
            #pragma unroll
            for (int j = 0; j < 4; j++) {
                (&va0.x)[j] = (&n0.x)[j] * f + (&va0.x)[j] * gf;
                (&va1.x)[j] = (&n1.x)[j] * f + (&va1.x)[j] * gf;
            }
        }
        const float* wp = Wt + (long)(2 * s_wp) * N + s_wn;
        we0 = *(const float4*)(wp);
        we1 = *(const float4*)(wp + 4);
        wo0 = *(const float4*)(wp + N);
        wo1 = *(const float4*)(wp + N + 4);
    }

    const int nch = K / 32;
    for (int i = 0; i < nch; i++) {
        uint32_t* S = sm + (i & 1) * STAGE_WORDS;

        // ---- stage A (hi/lo bf16x2, [pair][m]); j rotated by tg to avoid
        //      4-way store conflicts
        {
            float xs[8] = {va0.x, va0.y, va0.z, va0.w, va1.x, va1.y, va1.z, va1.w};
            #pragma unroll
            for (int jj = 0; jj < 4; jj++) {
                int j = (jj + tg) & 3;
                float e = xs[2 * j], o = xs[2 * j + 1];
                uint32_t h = pkbf(o, e);
                float2 hf = upbf(h);
                uint32_t l = pkbf(o - hf.y, e - hf.x);
                int off = (a_jb + j) * A2_PAD + s_ar;
                S[AHI_OFF + off] = h;
                S[ALO_OFF + off] = l;
            }
        }
        // ---- stage W (hi/lo bf16x2, [pair][n]), v4 stores
        {
            uint4 hh0, hh1, ll0, ll1;
            uint32_t* h0 = &hh0.x; uint32_t* h1 = &hh1.x;
            uint32_t* l0 = &ll0.x; uint32_t* l1 = &ll1.x;
            #pragma unroll
            for (int j = 0; j < 4; j++) {
                float e = (&we0.x)[j], o = (&wo0.x)[j];
                uint32_t h = pkbf(o, e);
                float2 hf = upbf(h);
                h0[j] = h;
                l0[j] = pkbf(o - hf.y, e - hf.x);
            }
            #pragma unroll
            for (int j = 0; j < 4; j++) {
                float e = (&we1.x)[j], o = (&wo1.x)[j];
                uint32_t h = pkbf(o, e);
                float2 hf = upbf(h);
                h1[j] = h;
                l1[j] = pkbf(o - hf.y, e - hf.x);
            }
            int wrow = s_wp * W2_PAD + s_wn;
            *(uint4*)(S + WHI_OFF + wrow)     = hh0;
            *(uint4*)(S + WHI_OFF + wrow + 4) = hh1;
            *(uint4*)(S + WLO_OFF + wrow)     = ll0;
            *(uint4*)(S + WLO_OFF + wrow + 4) = ll1;
        }
        __syncthreads();

        // ---- prefetch next chunk (overlaps compute)
        if (i + 1 < nch) {
            int kc = (i + 1) * 32;
            const float* ap = At + (long)s_ar * act_ld + kc + s_ak;
            va0 = *(const float4*)(ap);
            va1 = *(const float4*)(ap + 4);
            if (MIX) {
                const float* np = At2 + (long)s_ar * act_ld + kc + s_ak;
                float4 n0 = *(const float4*)(np);
                float4 n1 = *(const float4*)(np + 4);
                const float f = 1e-4f, gf = 1.0f - 1e-4f;
                #pragma unroll
                for (int j = 0; j < 4; j++) {
                    (&va0.x)[j] = (&n0.x)[j] * f + (&va0.x)[j] * gf;
                    (&va1.x)[j] = (&n1.x)[j] * f + (&va1.x)[j] * gf;
                }
            }
            const float* wp = Wt + (long)(kc + 2 * s_wp) * N + s_wn;
            we0 = *(const float4*)(wp);
            we1 = *(const float4*)(wp + 4);
            wo0 = *(const float4*)(wp + N);
            wo1 = *(const float4*)(wp + N + 4);
        }

        // ---- compute: 2 k16-steps
        #pragma unroll
        for (int ks = 0; ks < 2; ks++) {
            const int p0 = ks * 8 + tg;        // pairs for a0/a1, b0
            const int p1 = p0 + 4;             // pairs for a2/a3, b1
            uint32_t ah[2][4], al[2][4];
            #pragma unroll
            for (int mt = 0; mt < 2; mt++) {
                int m = wm * 32 + mt * 16 + g;
                ah[mt][0] = S[AHI_OFF + p0 * A2_PAD + m];
                ah[mt][1] = S[AHI_OFF + p0 * A2_PAD + m + 8];
                ah[mt][2] = S[AHI_OFF + p1 * A2_PAD + m];
                ah[mt][3] = S[AHI_OFF + p1 * A2_PAD + m + 8];
                al[mt][0] = S[ALO_OFF + p0 * A2_PAD + m];
                al[mt][1] = S[ALO_OFF + p0 * A2_PAD + m + 8];
                al[mt][2] = S[ALO_OFF + p1 * A2_PAD + m];
                al[mt][3] = S[ALO_OFF + p1 * A2_PAD + m + 8];
            }
            uint32_t bh[4][2], bl[4][2];
            #pragma unroll
            for (int nt = 0; nt < 4; nt++) {
                int n = wn * 32 + nt * 8 + g;
                bh[nt][0] = S[WHI_OFF + p0 * W2_PAD + n];
                bh[nt][1] = S[WHI_OFF + p1 * W2_PAD + n];
                bl[nt][0] = S[WLO_OFF + p0 * W2_PAD + n];
                bl[nt][1] = S[WLO_OFF + p1 * W2_PAD + n];
            }
            // Term-major: consecutive MMAs hit distinct accumulators.
            #pragma unroll
            for (int term = 0; term < 3; term++) {
                #pragma unroll
                for (int mt = 0; mt < 2; mt++) {
                    #pragma unroll
                    for (int nt = 0; nt < 4; nt++) {
                        const uint32_t* A = (term == 2) ? al[mt] : ah[mt];
                        const uint32_t* B = (term == 1) ? bl[nt] : bh[nt];
                        MMA_BF16(acc[mt][nt], A[0], A[1], A[2], A[3], B[0], B[1]);
                    }
                }
            }
        }
        // no trailing sync: next iteration stages the other buffer; reuse of
        // this buffer (i+2) is ordered by the sync at i+1.
    }
    __syncthreads();   // all compute done before smem reuse as epilogue stage

    // ---- epilogue: stage C (64 x 128) in smem for coalesced stores
    float* Csm = (float*)sm;               // [64][C_PAD]
    #pragma unroll
    for (int mt = 0; mt < 2; mt++) {
        #pragma unroll
        for (int nt = 0; nt < 4; nt++) {
            int row = wm * 32 + mt * 16 + g;
            int col = wn * 32 + nt * 8 + 2 * tg;
            float v0 = acc[mt][nt][0], v1 = acc[mt][nt][1];
            float v2 = acc[mt][nt][2], v3 = acc[mt][nt][3];
            if (GELU_EPI) {
                v0 = gelu_f(v0); v1 = gelu_f(v1);
                v2 = gelu_f(v2); v3 = gelu_f(v3);
            }
            *(float2*)(Csm + row * C_PAD + col)       = make_float2(v0, v1);
            *(float2*)(Csm + (row + 8) * C_PAD + col) = make_float2(v2, v3);
        }
    }
    __syncthreads();

    float* Cg = C + (long)t * c_t + ntile * 128;
    #pragma unroll
    for (int i = 0; i < 8; i++) {
        int idx = tid + i * 256;           // 2048 float4
        int b = idx >> 5, c4 = idx & 31;
        float4 v = *(float4*)(Csm + b * C_PAD + c4 * 4);
        *(float4*)(Cg + (long)b * c_ld + c4 * 4) = v;
    }
}

// ---------------------------------------------------------------------------
// Fused LayerNorm + latent noise + clamp. One block per row r=t*BB+b, D=1024.
// noise_z layout is [b][t][d].
// ---------------------------------------------------------------------------
__global__ __launch_bounds__(256) void ln_kernel(
    const float* __restrict__ H2, const float* __restrict__ noise_z,
    const float* __restrict__ gamma, const float* __restrict__ beta,
    float* __restrict__ Z)
{
    const int r = blockIdx.x;
    const int t = r >> 6;
    const int b = r & 63;
    const int tid = threadIdx.x;

    const float* h  = H2 + (long)r * DD;
    const float* nz = noise_z + ((long)b * TT + t) * DD;
    float*       z  = Z + (long)r * DD;

    float4 hv = *reinterpret_cast<const float4*>(h + tid * 4);
    float s  = hv.x + hv.y + hv.z + hv.w;
    float ss = hv.x * hv.x + hv.y * hv.y + hv.z * hv.z + hv.w * hv.w;

    #pragma unroll
    for (int off = 16; off > 0; off >>= 1) {
        s  += __shfl_xor_sync(0xffffffffu, s,  off);
        ss += __shfl_xor_sync(0xffffffffu, ss, off);
    }
    __shared__ float ws[8], wss[8];
    const int lane = tid & 31, wrp = tid >> 5;
    if (lane == 0) { ws[wrp] = s; wss[wrp] = ss; }
    __syncthreads();

    float mu = 0.f, m2 = 0.f;
    #pragma unroll
    for (int i = 0; i < 8; i++) { mu += ws[i]; m2 += wss[i]; }
    mu *= (1.0f / DD);
    float var  = m2 * (1.0f / DD) - mu * mu;
    float rstd = rsqrtf(var + 1e-5f);

    float4 nv = *reinterpret_cast<const float4*>(nz + tid * 4);
    float4 g4 = *reinterpret_cast<const float4*>(gamma + tid * 4);
    float4 b4 = *reinterpret_cast<const float4*>(beta + tid * 4);

    const float fl = 1e-3f, gl = 1.0f - 1e-3f;
    float4 ov; float v;
    v = (hv.x - mu) * rstd * g4.x + b4.x; v = nv.x * fl + v * gl; ov.x = fminf(1.0f, fmaxf(-1.0f, v));
    v = (hv.y - mu) * rstd * g4.y + b4.y; v = nv.y * fl + v * gl; ov.y = fminf(1.0f, fmaxf(-1.0f, v));
    v = (hv.z - mu) * rstd * g4.z + b4.z; v = nv.z * fl + v * gl; ov.z = fminf(1.0f, fmaxf(-1.0f, v));
    v = (hv.w - mu) * rstd * g4.w + b4.w; v = nv.w * fl + v * gl; ov.w = fminf(1.0f, fmaxf(-1.0f, v));
    *reinterpret_cast<float4*>(z + tid * 4) = ov;
}

extern "C" void kernel_launch(void* const* d_in, const int* in_sizes, int n_in,
                              void* d_out, int out_size) {
    const float* x       = (const float*)d_in[0];
    const float* noise_x = (const float*)d_in[1];
    const float* noise_z = (const float*)d_in[2];
    const float* enc_w1  = (const float*)d_in[3];   // [T][C][D]
    const float* enc_w2  = (const float*)d_in[4];   // [T][D][D]
    const float* dec_w1  = (const float*)d_in[5];   // [T][D][D]
    const float* dec_w2  = (const float*)d_in[6];   // [T][D][C]
    const float* ln_g    = (const float*)d_in[7];
    const float* ln_b    = (const float*)d_in[8];
    float* out = (float*)d_out;

    float *H, *H2, *Z, *G;
    cudaGetSymbolAddress((void**)&H,  g_H);
    cudaGetSymbolAddress((void**)&H2, g_H2);
    cudaGetSymbolAddress((void**)&Z,  g_Z);
    cudaGetSymbolAddress((void**)&G,  g_G);

    const int smem_bytes = SM_WORDS * 4;   // 53248
    cudaFuncSetAttribute(gemm_mma<true, true>,
                         cudaFuncAttributeMaxDynamicSharedMemorySize, smem_bytes);
    cudaFuncSetAttribute(gemm_mma<true, false>,
                         cudaFuncAttributeMaxDynamicSharedMemorySize, smem_bytes);
    cudaFuncSetAttribute(gemm_mma<false, false>,
                         cudaFuncAttributeMaxDynamicSharedMemorySize, smem_bytes);

    // 1) enc1: H = gelu((noise-mixed x chunk) @ enc_w1[t])   K=2048, N=1024
    gemm_mma<true, true><<<dim3(DD / 128, TT), 256, smem_bytes>>>(
        x, noise_x, (long)CC, TT * CC, enc_w1, DD, CC, H, (long)BB * DD, DD);

    // 2) enc2: H2 = H @ enc_w2[t]               K=1024, N=1024
    gemm_mma<false, false><<<dim3(DD / 128, TT), 256, smem_bytes>>>(
        H, nullptr, (long)BB * DD, DD, enc_w2, DD, DD, H2, (long)BB * DD, DD);

    // 3) LayerNorm + latent noise + clamp
    ln_kernel<<<TT * BB, 256>>>(H2, noise_z, ln_g, ln_b, Z);

    // 4) dec1: G = gelu(Z @ dec_w1[t])           K=1024, N=1024
    gemm_mma<true, false><<<dim3(DD / 128, TT), 256, smem_bytes>>>(
        Z, nullptr, (long)BB * DD, DD, dec_w1, DD, DD, G, (long)BB * DD, DD);

    // 5) dec2: out = G @ dec_w2[t]               K=1024, N=2048
    gemm_mma<false, false><<<dim3(CC / 128, TT), 256, smem_bytes>>>(
        G, nullptr, (long)BB * DD, DD, dec_w2, CC, DD, out, (long)CC, TT * CC);
}

// round 15
// speedup vs baseline: 1.1890x; 1.1890x over previous
#include <cuda_runtime.h>
#include <cuda_bf16.h>
#include <math.h>
#include <stdint.h>

#define BB 64
#define TT 32
#define CC 2048
#define DD 1024

// Scratch (__device__ globals; allocation-free rule)
__device__ float g_H [TT * BB * DD];
__device__ float g_H2[TT * BB * DD];
__device__ float g_Z [TT * BB * DD];
__device__ float g_G [TT * BB * DD];

__device__ __forceinline__ float gelu_f(float x) {
    return 0.5f * x * (1.0f + erff(x * 0.70710678118654752440f));
}

// pack two floats -> bf16x2 word: lo16 = bf16(e), hi16 = bf16(o)
__device__ __forceinline__ uint32_t pkbf(float o, float e) {
    uint32_t r;
    asm("cvt.rn.bf16x2.f32 %0, %1, %2;" : "=r"(r) : "f"(o), "f"(e));
    return r;
}
__device__ __forceinline__ float2 upbf(uint32_t w) {
    __nv_bfloat162 h = *reinterpret_cast<__nv_bfloat162*>(&w);
    return __bfloat1622float2(h);
}

// acc += A(16x16 bf16) @ B(16x8 bf16), fp32 accum
#define MMA_BF16(c, a0, a1, a2, a3, b0, b1) \
    asm volatile("mma.sync.aligned.m16n8k16.row.col.f32.bf16.bf16.f32 " \
                 "{%0,%1,%2,%3}, {%4,%5,%6,%7}, {%8,%9}, {%0,%1,%2,%3};" \
                 : "+f"((c)[0]), "+f"((c)[1]), "+f"((c)[2]), "+f"((c)[3]) \
                 : "r"(a0), "r"(a1), "r"(a2), "r"(a3), "r"(b0), "r"(b1))

#define LDMX4(d, addr) \
    asm volatile("ldmatrix.sync.aligned.m8n8.x4.shared.b16 {%0,%1,%2,%3}, [%4];" \
                 : "=r"((d)[0]), "=r"((d)[1]), "=r"((d)[2]), "=r"((d)[3]) : "r"(addr))
#define LDMX4T(d, addr) \
    asm volatile("ldmatrix.sync.aligned.m8n8.x4.trans.shared.b16 {%0,%1,%2,%3}, [%4];" \
                 : "=r"((d)[0]), "=r"((d)[1]), "=r"((d)[2]), "=r"((d)[3]) : "r"(addr))

// Per-stage layout (32-bit words):
//  A hi: [m=64][k-pair 16, stride 20]  -> 1280 words   (ldmatrix rows: m*20 conflict-free)
//  A lo: +1280
//  W hi: [k=32][n bf16x2 64, stride 68] -> 2176 words  (rows k*68 -> distinct bank quads)
//  W lo: +2176
#define AHI_W 0
#define ALO_W 1280
#define WHI_W 2560
#define WLO_W 4736
#define STAGE_WORDS 6912
#define SM_WORDS 13824          // 2 stages = 55296 B; epilogue (64*132=8448 w) fits
#define A_STRIDE 20
#define W_STRIDE 68
#define C_PAD 132

// ---------------------------------------------------------------------------
// Batched GEMM, 3x-split bf16 m16n8k16, double-buffered smem, ldmatrix frags:
//   C[t](64 x N) = Act[t](64 x K) @ W[t](K x N)
// Block: 256 thr, tile 64m x 128n, BK=32 (2 k16-steps).
// MIX: A := Act2*1e-4 + Act*(1-1e-4) on load (fused input-noise for enc1).
// ---------------------------------------------------------------------------
template<bool GELU_EPI, bool MIX>
__global__ __launch_bounds__(256, 2) void gemm_mma(
    const float* __restrict__ Act, const float* __restrict__ Act2,
    long act_t, int act_ld,
    const float* __restrict__ W, int N, int K,
    float* __restrict__ C, long c_t, int c_ld)
{
    extern __shared__ __align__(16) uint32_t sm[];
    const int t     = blockIdx.y;
    const int ntile = blockIdx.x;
    const int tid   = threadIdx.x;
    const int wid   = tid >> 5;
    const int lid   = tid & 31;
    const int wm    = wid & 1;
    const int wn    = wid >> 1;
    const int g     = lid >> 2;
    const int tg    = lid & 3;

    const float* At  = Act + (long)t * act_t;
    const float* At2 = MIX ? (Act2 + (long)t * act_t) : nullptr;
    const float* Wt  = W + (long)t * K * N + ntile * 128;

    float acc[2][4][4];
    #pragma unroll
    for (int i = 0; i < 2; i++)
        #pragma unroll
        for (int j = 0; j < 4; j++)
            #pragma unroll
            for (int r = 0; r < 4; r++) acc[i][j][r] = 0.f;

    // global load maps
    const int s_ar = tid >> 2;             // A row 0..63
    const int s_ak = (tid & 3) * 8;        // A k base (8 floats = 4 pairs)
    const int s_wp = tid >> 4;             // W k-pair 0..15 (rows 2p, 2p+1)
    const int s_wn = (tid & 15) * 8;       // W n base (8 floats)
    const int a_jb = s_ak >> 1;            // A k-pair base 0,4,8,12

    const uint32_t sbase = (uint32_t)__cvta_generic_to_shared(sm);

    // ldmatrix lane address components (word units)
    const int lm_row = (lid & 7) + ((lid >> 3) & 1) * 8;   // 0..15
    const int lm_hi  = (lid >> 4) & 1;                      // 0..1
    // A: matrices (m0-7,k0-7),(m8-15,k0-7),(m0-7,k8-15),(m8-15,k8-15)
    const uint32_t a_w0 = (uint32_t)((wm * 32 + 0  * 16 + lm_row) * A_STRIDE + lm_hi * 4);
    const uint32_t a_w1 = (uint32_t)((wm * 32 + 1  * 16 + lm_row) * A_STRIDE + lm_hi * 4);
    // B: matrices (k0-7,n0-7),(k8-15,n0-7),(k0-7,n8-15),(k8-15,n8-15) per nt-pair
    const uint32_t b_w0 = (uint32_t)(lm_row * W_STRIDE + wn * 16 + 0 * 8 + lm_hi * 4);
    const uint32_t b_w1 = (uint32_t)(lm_row * W_STRIDE + wn * 16 + 1 * 8 + lm_hi * 4);

    // ---- prefetch chunk 0
    float4 va0, va1, we0, we1, wo0, wo1;
    {
        const float* ap = At + (long)s_ar * act_ld + s_ak;
        va0 = *(const float4*)(ap);
        va1 = *(const float4*)(ap + 4);
        if (MIX) {
            const float* np = At2 + (long)s_ar * act_ld + s_ak;
            float4 n0 = *(const float4*)(np);
            float4 n1 = *(const float4*)(np + 4);
            const float f = 1e-4f, gf = 1.0f - 1e-4f;
            #pragma unroll
            for (int j = 0; j < 4; j++) {
                (&va0.x)[j] = (&n0.x)[j] * f + (&va0.x)[j] * gf;
                (&va1.x)[j] = (&n1.x)[j] * f + (&va1.x)[j] * gf;
            }
        }
        const float* wp = Wt + (long)(2 * s_wp) * N + s_wn;
        we0 = *(const float4*)(wp);
        we1 = *(const float4*)(wp + 4);
        wo0 = *(const float4*)(wp + N);
        wo1 = *(const float4*)(wp + N + 4);
    }

    const int nch = K / 32;
    for (int i = 0; i < nch; i++) {
        uint32_t* S = sm + (i & 1) * STAGE_WORDS;
        const uint32_t Sb = sbase + (uint32_t)((i & 1) * STAGE_WORDS * 4);

        // ---- stage A: [m][k-pair] hi/lo, one uint4 each
        {
            float xs[8] = {va0.x, va0.y, va0.z, va0.w, va1.x, va1.y, va1.z, va1.w};
            uint4 hq, lq;
            uint32_t* hp = &hq.x; uint32_t* lp = &lq.x;
            #pragma unroll
            for (int q = 0; q < 4; q++) {
                float e = xs[2 * q], o = xs[2 * q + 1];
                uint32_t h = pkbf(o, e);
                float2 hf = upbf(h);
                hp[q] = h;
                lp[q] = pkbf(o - hf.y, e - hf.x);
            }
            int off = s_ar * A_STRIDE + a_jb;
            *(uint4*)(S + AHI_W + off) = hq;
            *(uint4*)(S + ALO_W + off) = lq;
        }
        // ---- stage W: [k][n] elementwise bf16 (n-contiguous), hi/lo, rows 2p & 2p+1
        {
            float wek[8] = {we0.x, we0.y, we0.z, we0.w, we1.x, we1.y, we1.z, we1.w};
            float wok[8] = {wo0.x, wo0.y, wo0.z, wo0.w, wo1.x, wo1.y, wo1.z, wo1.w};
            uint4 he, le, ho, lo4;
            uint32_t* hep = &he.x; uint32_t* lep = &le.x;
            uint32_t* hop = &ho.x; uint32_t* lop = &lo4.x;
            #pragma unroll
            for (int q = 0; q < 4; q++) {
                float e0 = wek[2 * q], o0 = wek[2 * q + 1];   // n-adjacent, k = 2p
                uint32_t h0 = pkbf(o0, e0);
                float2 f0 = upbf(h0);
                hep[q] = h0;
                lep[q] = pkbf(o0 - f0.y, e0 - f0.x);
                float e1 = wok[2 * q], o1 = wok[2 * q + 1];   // k = 2p+1
                uint32_t h1 = pkbf(o1, e1);
                float2 f1 = upbf(h1);
                hop[q] = h1;
                lop[q] = pkbf(o1 - f1.y, e1 - f1.x);
            }
            int nw = (tid & 15) * 4;                          // n word base
            int r0 = (2 * s_wp) * W_STRIDE + nw;
            int r1 = r0 + W_STRIDE;
            *(uint4*)(S + WHI_W + r0) = he;
            *(uint4*)(S + WHI_W + r1) = ho;
            *(uint4*)(S + WLO_W + r0) = le;
            *(uint4*)(S + WLO_W + r1) = lo4;
        }
        __syncthreads();

        // ---- prefetch next chunk (overlaps compute)
        if (i + 1 < nch) {
            int kc = (i + 1) * 32;
            const float* ap = At + (long)s_ar * act_ld + kc + s_ak;
            va0 = *(const float4*)(ap);
            va1 = *(const float4*)(ap + 4);
            if (MIX) {
                const float* np = At2 + (long)s_ar * act_ld + kc + s_ak;
                float4 n0 = *(const float4*)(np);
                float4 n1 = *(const float4*)(np + 4);
                const float f = 1e-4f, gf = 1.0f - 1e-4f;
                #pragma unroll
                for (int j = 0; j < 4; j++) {
                    (&va0.x)[j] = (&n0.x)[j] * f + (&va0.x)[j] * gf;
                    (&va1.x)[j] = (&n1.x)[j] * f + (&va1.x)[j] * gf;
                }
            }
            const float* wp = Wt + (long)(kc + 2 * s_wp) * N + s_wn;
            we0 = *(const float4*)(wp);
            we1 = *(const float4*)(wp + 4);
            wo0 = *(const float4*)(wp + N);
            wo1 = *(const float4*)(wp + N + 4);
        }

        // ---- compute: 2 k16-steps, fragments via ldmatrix
        #pragma unroll
        for (int ks = 0; ks < 2; ks++) {
            uint32_t ah[2][4], al[2][4];
            {
                uint32_t a0 = Sb + (AHI_W + a_w0 + ks * 8) * 4;
                uint32_t a1 = Sb + (AHI_W + a_w1 + ks * 8) * 4;
                LDMX4(ah[0], a0);
                LDMX4(ah[1], a1);
                LDMX4(al[0], a0 + (ALO_W - AHI_W) * 4);
                LDMX4(al[1], a1 + (ALO_W - AHI_W) * 4);
            }
            uint32_t bh[2][4], bl[2][4];   // [nt-pair][b0e,b1e,b0o,b1o]
            {
                uint32_t b0 = Sb + (WHI_W + b_w0 + ks * 16 * W_STRIDE) * 4;
                uint32_t b1 = Sb + (WHI_W + b_w1 + ks * 16 * W_STRIDE) * 4;
                LDMX4T(bh[0], b0);
                LDMX4T(bh[1], b1);
                LDMX4T(bl[0], b0 + (WLO_W - WHI_W) * 4);
                LDMX4T(bl[1], b1 + (WLO_W - WHI_W) * 4);
            }
            #pragma unroll
            for (int mt = 0; mt < 2; mt++) {
                #pragma unroll
                for (int nt = 0; nt < 4; nt++) {
                    const int np_ = nt >> 1, sel = (nt & 1) * 2;
                    uint32_t b0h = bh[np_][sel], b1h = bh[np_][sel + 1];
                    uint32_t b0l = bl[np_][sel], b1l = bl[np_][sel + 1];
                    MMA_BF16(acc[mt][nt], ah[mt][0], ah[mt][1], ah[mt][2], ah[mt][3], b0h, b1h);
                    MMA_BF16(acc[mt][nt], ah[mt][0], ah[mt][1], ah[mt][2], ah[mt][3], b0l, b1l);
                    MMA_BF16(acc[mt][nt], al[mt][0], al[mt][1], al[mt][2], al[mt][3], b0h, b1h);
                }
            }
        }
        // no trailing sync: next iteration stages the other buffer; reuse of
        // this buffer (i+2) is ordered by the sync at i+1.
    }
    __syncthreads();   // all compute done before smem reuse as epilogue stage

    // ---- epilogue: stage C (64 x 128) in smem for coalesced stores
    float* Csm = (float*)sm;               // [64][C_PAD]
    #pragma unroll
    for (int mt = 0; mt < 2; mt++) {
        #pragma unroll
        for (int nt = 0; nt < 4; nt++) {
            int row = wm * 32 + mt * 16 + g;
            int col = wn * 32 + nt * 8 + 2 * tg;
            float v0 = acc[mt][nt][0], v1 = acc[mt][nt][1];
            float v2 = acc[mt][nt][2], v3 = acc[mt][nt][3];
            if (GELU_EPI) {
                v0 = gelu_f(v0); v1 = gelu_f(v1);
                v2 = gelu_f(v2); v3 = gelu_f(v3);
            }
            *(float2*)(Csm + row * C_PAD + col)       = make_float2(v0, v1);
            *(float2*)(Csm + (row + 8) * C_PAD + col) = make_float2(v2, v3);
        }
    }
    __syncthreads();

    float* Cg = C + (long)t * c_t + ntile * 128;
    #pragma unroll
    for (int i = 0; i < 8; i++) {
        int idx = tid + i * 256;           // 2048 float4
        int b = idx >> 5, c4 = idx & 31;
        float4 v = *(float4*)(Csm + b * C_PAD + c4 * 4);
        *(float4*)(Cg + (long)b * c_ld + c4 * 4) = v;
    }
}

// ---------------------------------------------------------------------------
// Fused LayerNorm + latent noise + clamp. One block per row r=t*BB+b, D=1024.
// noise_z layout is [b][t][d].
// ---------------------------------------------------------------------------
__global__ __launch_bounds__(256) void ln_kernel(
    const float* __restrict__ H2, const float* __restrict__ noise_z,
    const float* __restrict__ gamma, const float* __restrict__ beta,
    float* __restrict__ Z)
{
    const int r = blockIdx.x;
    const int t = r >> 6;
    const int b = r & 63;
    const int tid = threadIdx.x;

    const float* h  = H2 + (long)r * DD;
    const float* nz = noise_z + ((long)b * TT + t) * DD;
    float*       z  = Z + (long)r * DD;

    float4 hv = *reinterpret_cast<const float4*>(h + tid * 4);
    float s  = hv.x + hv.y + hv.z + hv.w;
    float ss = hv.x * hv.x + hv.y * hv.y + hv.z * hv.z + hv.w * hv.w;

    #pragma unroll
    for (int off = 16; off > 0; off >>= 1) {
        s  += __shfl_xor_sync(0xffffffffu, s,  off);
        ss += __shfl_xor_sync(0xffffffffu, ss, off);
    }
    __shared__ float ws[8], wss[8];
    const int lane = tid & 31, wrp = tid >> 5;
    if (lane == 0) { ws[wrp] = s; wss[wrp] = ss; }
    __syncthreads();

    float mu = 0.f, m2 = 0.f;
    #pragma unroll
    for (int i = 0; i < 8; i++) { mu += ws[i]; m2 += wss[i]; }
    mu *= (1.0f / DD);
    float var  = m2 * (1.0f / DD) - mu * mu;
    float rstd = rsqrtf(var + 1e-5f);

    float4 nv = *reinterpret_cast<const float4*>(nz + tid * 4);
    float4 g4 = *reinterpret_cast<const float4*>(gamma + tid * 4);
    float4 b4 = *reinterpret_cast<const float4*>(beta + tid * 4);

    const float fl = 1e-3f, gl = 1.0f - 1e-3f;
    float4 ov; float v;
    v = (hv.x - mu) * rstd * g4.x + b4.x; v = nv.x * fl + v * gl; ov.x = fminf(1.0f, fmaxf(-1.0f, v));
    v = (hv.y - mu) * rstd * g4.y + b4.y; v = nv.y * fl + v * gl; ov.y = fminf(1.0f, fmaxf(-1.0f, v));
    v = (hv.z - mu) * rstd * g4.z + b4.z; v = nv.z * fl + v * gl; ov.z = fminf(1.0f, fmaxf(-1.0f, v));
    v = (hv.w - mu) * rstd * g4.w + b4.w; v = nv.w * fl + v * gl; ov.w = fminf(1.0f, fmaxf(-1.0f, v));
    *reinterpret_cast<float4*>(z + tid * 4) = ov;
}

extern "C" void kernel_launch(void* const* d_in, const int* in_sizes, int n_in,
                              void* d_out, int out_size) {
    const float* x       = (const float*)d_in[0];
    const float* noise_x = (const float*)d_in[1];
    const float* noise_z = (const float*)d_in[2];
    const float* enc_w1  = (const float*)d_in[3];   // [T][C][D]
    const float* enc_w2  = (const float*)d_in[4];   // [T][D][D]
    const float* dec_w1  = (const float*)d_in[5];   // [T][D][D]
    const float* dec_w2  = (const float*)d_in[6];   // [T][D][C]
    const float* ln_g    = (const float*)d_in[7];
    const float* ln_b    = (const float*)d_in[8];
    float* out = (float*)d_out;

    float *H, *H2, *Z, *G;
    cudaGetSymbolAddress((void**)&H,  g_H);
    cudaGetSymbolAddress((void**)&H2, g_H2);
    cudaGetSymbolAddress((void**)&Z,  g_Z);
    cudaGetSymbolAddress((void**)&G,  g_G);

    const int smem_bytes = SM_WORDS * 4;   // 55296
    cudaFuncSetAttribute(gemm_mma<true, true>,
                         cudaFuncAttributeMaxDynamicSharedMemorySize, smem_bytes);
    cudaFuncSetAttribute(gemm_mma<true, false>,
                         cudaFuncAttributeMaxDynamicSharedMemorySize, smem_bytes);
    cudaFuncSetAttribute(gemm_mma<false, false>,
                         cudaFuncAttributeMaxDynamicSharedMemorySize, smem_bytes);

    // 1) enc1: H = gelu((noise-mixed x chunk) @ enc_w1[t])   K=2048, N=1024
    gemm_mma<true, true><<<dim3(DD / 128, TT), 256, smem_bytes>>>(
        x, noise_x, (long)CC, TT * CC, enc_w1, DD, CC, H, (long)BB * DD, DD);

    // 2) enc2: H2 = H @ enc_w2[t]               K=1024, N=1024
    gemm_mma<false, false><<<dim3(DD / 128, TT), 256, smem_bytes>>>(
        H, nullptr, (long)BB * DD, DD, enc_w2, DD, DD, H2, (long)BB * DD, DD);

    // 3) LayerNorm + latent noise + clamp
    ln_kernel<<<TT * BB, 256>>>(H2, noise_z, ln_g, ln_b, Z);

    // 4) dec1: G = gelu(Z @ dec_w1[t])           K=1024, N=1024
    gemm_mma<true, false><<<dim3(DD / 128, TT), 256, smem_bytes>>>(
        Z, nullptr, (long)BB * DD, DD, dec_w1, DD, DD, G, (long)BB * DD, DD);

    // 5) dec2: out = G @ dec_w2[t]               K=1024, N=2048
    gemm_mma<false, false><<<dim3(CC / 128, TT), 256, smem_bytes>>>(
        G, nullptr, (long)BB * DD, DD, dec_w2, CC, DD, out, (long)CC, TT * CC);
}